// round 10
// baseline (speedup 1.0000x reference)
#include <cuda_runtime.h>
#include <cuda_fp16.h>
#include <cstdint>
#include <math.h>

#define NTHREADS 256
#define TMC      64
#define NSTEP    32          // 16 k16-chunks x {hi,lo}
#define B_STG    12288       // 256 n * 48B
#define B_STRIDE 48

#define OFF_AHI  0                    // [64 m][512B] XOR-swizzled
#define OFF_ALO  32768
#define OFF_B    65536                // 3 stages * 12288 -> 102400
#define OFF_B2S  102400
#define OFF_W3S  103424
#define OFF_B3S  106496
#define OFF_RS   106512
#define SMEM_BYTES 107280             // *2 = 214.6KB -> 2 CTA/SM
// transients live in B stage-2 region until mainloop refills it (step s=2):
#define OFF_W1T  (OFF_B + 2 * B_STG)  // 90112
#define OFF_B1T  (OFF_W1T + 3072)
#define OFF_XS   (OFF_B1T + 1024)     // 2304 B -> ends 96512 < 102400
#define OFF_PSUM OFF_B                // epilogue reuse

// ---------------- global scratch: W2^T split fp16 hi/lo, [n][k] 512B rows ----
__device__ __align__(128) __half g_w2t_hi[256 * 256];
__device__ __align__(128) __half g_w2t_lo[256 * 256];

__device__ __forceinline__ uint32_t smem_u32(const void* p) {
    uint32_t a;
    asm("{ .reg .u64 t; cvta.to.shared.u64 t, %1; cvt.u32.u64 %0, t; }" : "=r"(a) : "l"(p));
    return a;
}

#define LDSM4(r, a)                                                           \
    asm volatile("ldmatrix.sync.aligned.m8n8.x4.shared.b16 {%0,%1,%2,%3}, [%4];" \
        : "=r"((r)[0]), "=r"((r)[1]), "=r"((r)[2]), "=r"((r)[3]) : "r"(a))

#define MMA_F16(acc, A, b0, b1)                                               \
    asm volatile(                                                             \
        "mma.sync.aligned.m16n8k16.row.col.f32.f16.f16.f32 "                  \
        "{%0,%1,%2,%3}, {%4,%5,%6,%7}, {%8,%9}, {%0,%1,%2,%3};"               \
        : "+f"((acc)[0]), "+f"((acc)[1]), "+f"((acc)[2]), "+f"((acc)[3])      \
        : "r"((A)[0]), "r"((A)[1]), "r"((A)[2]), "r"((A)[3]),                 \
          "r"(b0), "r"(b1))

#define CP_ASYNC16(dst, src)                                                  \
    asm volatile("cp.async.cg.shared.global [%0], [%1], 16;" :: "r"(dst), "l"(src) : "memory")
#define CP_COMMIT()  asm volatile("cp.async.commit_group;" ::: "memory")
#define CP_WAIT1()   asm volatile("cp.async.wait_group 1;" ::: "memory")

// ---------------- kernel 1: transpose + split W2 -> fp16 hi/lo [n][k] -------
__global__ void prep_w2(const float* __restrict__ W2) {
    __shared__ float tile[32][33];
    int bx = blockIdx.x & 7;        // n tile
    int by = blockIdx.x >> 3;       // k tile
    int tx = threadIdx.x & 31;
    int ty = threadIdx.x >> 5;
    #pragma unroll
    for (int i = 0; i < 32; i += 8)
        tile[ty + i][tx] = W2[(by * 32 + ty + i) * 256 + bx * 32 + tx];
    __syncthreads();
    #pragma unroll
    for (int i = 0; i < 32; i += 8) {
        int n = bx * 32 + ty + i;
        int k = by * 32 + tx;
        float v = tile[tx][ty + i];                 // W2[k][n]
        __half h = __float2half_rn(v);
        g_w2t_hi[n * 256 + k] = h;
        g_w2t_lo[n * 256 + k] = __float2half_rn(v - __half2float(h));
    }
}

// issue one pipeline step: step s = k16-chunk (s>>1), mat hi(0)/lo(1) = s&1
__device__ __forceinline__ void issue_step(uint32_t sb, const char* ghi,
                                           const char* glo, int s, int tid)
{
    const char* src = (s & 1) ? glo : ghi;
    int c = s >> 1;
    uint32_t stg = sb + OFF_B + (uint32_t)(s % 3) * B_STG;
    #pragma unroll
    for (int u = 0; u < 2; u++) {
        int gi  = u * NTHREADS + tid;     // 0..511
        int n   = gi >> 1;
        int seg = gi & 1;
        CP_ASYNC16(stg + n * B_STRIDE + seg * 16,
                   src + n * 512 + c * 32 + seg * 16);
    }
}

// ---------------- kernel 2: fused main ----------------
__global__ __launch_bounds__(NTHREADS, 2)
void nn_adiab_mma(const float* __restrict__ x,
                  const float* __restrict__ W1,
                  const float* __restrict__ b1,
                  const float* __restrict__ b2,
                  const float* __restrict__ W3,
                  const float* __restrict__ b3,
                  float* __restrict__ out,
                  int B)
{
    extern __shared__ __align__(128) char smem[];
    const uint32_t sb = smem_u32(smem);
    const int tid  = threadIdx.x;
    const int wid  = tid >> 5;
    const int lane = tid & 31;
    const int g    = lane >> 2;
    const int t    = lane & 3;
    const int wy   = wid & 1;        // 2 m-warps x 32 rows
    const int wx   = wid >> 1;       // 4 n-warps x 64 cols
    const int m0w  = wy * 32;
    const int n0w  = wx * 64;
    const int row0 = blockIdx.x * TMC;

    const char* ghi = (const char*)g_w2t_hi;
    const char* glo = (const char*)g_w2t_lo;

    // ---- prefetch steps 0,1 (stages 0,1); stage 2 holds transients ----
    issue_step(sb, ghi, glo, 0, tid); CP_COMMIT();
    issue_step(sb, ghi, glo, 1, tid); CP_COMMIT();

    float* w1s = (float*)(smem + OFF_W1T);
    float* b1s = (float*)(smem + OFF_B1T);
    float* xs  = (float*)(smem + OFF_XS);
    float* b2s = (float*)(smem + OFF_B2S);
    float* w3s = (float*)(smem + OFF_W3S);
    float* b3s = (float*)(smem + OFF_B3S);
    float* rs  = (float*)(smem + OFF_RS);

    for (int i = tid; i < 768; i += NTHREADS) w1s[i] = W1[i];
    for (int i = tid; i < 256; i += NTHREADS) { b1s[i] = b1[i]; b2s[i] = b2[i]; }
    for (int i = tid; i < 768; i += NTHREADS) w3s[i] = W3[i];
    if (tid < 3) b3s[tid] = b3[tid];
    for (int i = tid; i < TMC * 9; i += NTHREADS) {
        int r = row0 + i / 9;
        xs[i] = (r < B) ? x[(size_t)row0 * 9 + i] : 0.f;
    }
    __syncthreads();

    // ---- pairwise distances ----
    if (tid < TMC) {
        const float* p = xs + tid * 9;
        float ax=p[0],ay=p[1],az=p[2], bx=p[3],by=p[4],bz=p[5], cx=p[6],cy=p[7],cz=p[8];
        float d0x=ax-bx, d0y=ay-by, d0z=az-bz;
        float d1x=ax-cx, d1y=ay-cy, d1z=az-cz;
        float d2x=bx-cx, d2y=by-cy, d2z=bz-cz;
        rs[tid*3+0] = sqrtf(d0x*d0x + d0y*d0y + d0z*d0z);
        rs[tid*3+1] = sqrtf(d1x*d1x + d1y*d1y + d1z*d1z);
        rs[tid*3+2] = sqrtf(d2x*d2x + d2y*d2y + d2z*d2z);
    }
    __syncthreads();

    // ---- build FULL A = split-fp16(h1): [64 m][256 k], XOR-swizzled ----
    // 8192 k-pairs, 32 per thread
    #pragma unroll 4
    for (int i = 0; i < 32; i++) {
        int flat = i * NTHREADS + tid;
        int m  = flat >> 7;
        int kp = flat & 127;
        int k  = kp * 2;
        float r0 = rs[m*3+0], r1 = rs[m*3+1], r2 = rs[m*3+2];
        float v0 = fmaf(r0, w1s[k],   fmaf(r1, w1s[256+k],   fmaf(r2, w1s[512+k],   b1s[k])));
        float v1 = fmaf(r0, w1s[k+1], fmaf(r1, w1s[256+k+1], fmaf(r2, w1s[512+k+1], b1s[k+1])));
        v0 = fmaxf(v0, 0.f);
        v1 = fmaxf(v1, 0.f);
        __half2 hp = __floats2half2_rn(v0, v1);
        float h0f = __half2float(__low2half(hp));
        float h1f = __half2float(__high2half(hp));
        __half2 lp = __floats2half2_rn(v0 - h0f, v1 - h1f);
        uint32_t kb = (uint32_t)k * 2;
        uint32_t off = (uint32_t)m * 512 + (kb ^ (((uint32_t)m & 7) << 4));
        *(uint32_t*)(smem + OFF_AHI + off) = *(uint32_t*)&hp;
        *(uint32_t*)(smem + OFF_ALO + off) = *(uint32_t*)&lp;
    }
    __syncthreads();     // A done; transients dead -> stage 2 free for step 2

    // ---- per-thread ldmatrix offsets ----
    const int jj = lane >> 3, rr = lane & 7;
    const int rowA  = m0w + ((jj & 1) << 3) + rr;
    const uint32_t rmask = ((uint32_t)(rowA & 7)) << 4;
    const uint32_t kOffA = (uint32_t)((jj >> 1) << 4);     // 0 or 16 B
    const uint32_t aHi0 = sb + OFF_AHI + (uint32_t)rowA * 512;
    const uint32_t aHi1 = aHi0 + 16 * 512;
    const uint32_t aLo0 = sb + OFF_ALO + (uint32_t)rowA * 512;
    const uint32_t aLo1 = aLo0 + 16 * 512;
    const int nOffB = ((jj >> 1) << 3) + rr;
    const int kOffB = (jj & 1) << 4;                       // 0 or 16 B
    const uint32_t boffB = (uint32_t)(n0w + nOffB) * B_STRIDE + kOffB;

    // ---- accumulators ----
    float acc[2][8][4];
    #pragma unroll
    for (int mt = 0; mt < 2; mt++)
        #pragma unroll
        for (int nt = 0; nt < 8; nt++)
            #pragma unroll
            for (int q = 0; q < 4; q++) acc[mt][nt][q] = 0.f;

    // ---- mainloop: 16 k16 chunks as (hi, lo) step pairs, 3-stage B ----
    uint32_t ah[2][4], al[2][4];
    for (int c = 0; c < 16; c++) {
        // === hi step s = 2c ===
        {
            const int s = 2 * c;
            CP_WAIT1();
            __syncthreads();
            if (s + 2 < NSTEP) issue_step(sb, ghi, glo, s + 2, tid);
            CP_COMMIT();

            const uint32_t ka = ((uint32_t)c * 32 + kOffA) ^ rmask;
            LDSM4(ah[0], aHi0 + ka);
            LDSM4(ah[1], aHi1 + ka);
            LDSM4(al[0], aLo0 + ka);
            LDSM4(al[1], aLo1 + ka);

            const uint32_t bb = sb + OFF_B + (uint32_t)(s % 3) * B_STG + boffB;
            uint32_t bh[16];
            LDSM4(bh,      bb + 0 * (8 * B_STRIDE));
            LDSM4(bh + 4,  bb + 2 * (8 * B_STRIDE));
            LDSM4(bh + 8,  bb + 4 * (8 * B_STRIDE));
            LDSM4(bh + 12, bb + 6 * (8 * B_STRIDE));
            #pragma unroll
            for (int mt = 0; mt < 2; mt++)
                #pragma unroll
                for (int q = 0; q < 8; q++)
                    MMA_F16(acc[mt][q], ah[mt], bh[2 * q], bh[2 * q + 1]);
            #pragma unroll
            for (int mt = 0; mt < 2; mt++)
                #pragma unroll
                for (int q = 0; q < 8; q++)
                    MMA_F16(acc[mt][q], al[mt], bh[2 * q], bh[2 * q + 1]);
        }
        // === lo step s = 2c+1 (reuses ah from hi step) ===
        {
            const int s = 2 * c + 1;
            CP_WAIT1();
            __syncthreads();
            if (s + 2 < NSTEP) issue_step(sb, ghi, glo, s + 2, tid);
            CP_COMMIT();

            const uint32_t bb = sb + OFF_B + (uint32_t)(s % 3) * B_STG + boffB;
            uint32_t bl[16];
            LDSM4(bl,      bb + 0 * (8 * B_STRIDE));
            LDSM4(bl + 4,  bb + 2 * (8 * B_STRIDE));
            LDSM4(bl + 8,  bb + 4 * (8 * B_STRIDE));
            LDSM4(bl + 12, bb + 6 * (8 * B_STRIDE));
            #pragma unroll
            for (int mt = 0; mt < 2; mt++)
                #pragma unroll
                for (int q = 0; q < 8; q++)
                    MMA_F16(acc[mt][q], ah[mt], bl[2 * q], bl[2 * q + 1]);
        }
    }

    // ---- epilogue: bias2 + relu + layer3 partials ----
    __syncthreads();
    float* psum = (float*)(smem + OFF_PSUM);   // [4 wx][64 row][3]
    #pragma unroll
    for (int mt = 0; mt < 2; mt++) {
        float p[2][3];
        p[0][0]=p[0][1]=p[0][2]=0.f;
        p[1][0]=p[1][1]=p[1][2]=0.f;
        #pragma unroll
        for (int nt = 0; nt < 8; nt++) {
            int n  = n0w + nt * 8 + 2 * t;
            int n2 = n + 1;
            float bn = b2s[n], bn2 = b2s[n2];
            float h00 = fmaxf(acc[mt][nt][0] + bn,  0.f);
            float h01 = fmaxf(acc[mt][nt][1] + bn2, 0.f);
            float h10 = fmaxf(acc[mt][nt][2] + bn,  0.f);
            float h11 = fmaxf(acc[mt][nt][3] + bn2, 0.f);
            #pragma unroll
            for (int j = 0; j < 3; j++) {
                float wA = w3s[n * 3 + j], wB = w3s[n2 * 3 + j];
                p[0][j] = fmaf(h00, wA, fmaf(h01, wB, p[0][j]));
                p[1][j] = fmaf(h10, wA, fmaf(h11, wB, p[1][j]));
            }
        }
        #pragma unroll
        for (int s = 0; s < 2; s++)
            #pragma unroll
            for (int j = 0; j < 3; j++) {
                p[s][j] += __shfl_xor_sync(0xffffffffu, p[s][j], 1);
                p[s][j] += __shfl_xor_sync(0xffffffffu, p[s][j], 2);
            }
        if (t == 0) {
            #pragma unroll
            for (int s = 0; s < 2; s++) {
                int rloc = m0w + mt * 16 + g + 8 * s;
                #pragma unroll
                for (int j = 0; j < 3; j++)
                    psum[(wx * TMC + rloc) * 3 + j] = p[s][j];
            }
        }
    }
    __syncthreads();

    // ---- final cross-warp reduce + eigen + store ----
    if (tid < TMC) {
        int gr = row0 + tid;
        if (gr < B) {
            float w0 = b3s[0], w1 = b3s[1], w2 = b3s[2];
            #pragma unroll
            for (int q = 0; q < 4; q++) {
                w0 += psum[(q * TMC + tid) * 3 + 0];
                w1 += psum[(q * TMC + tid) * 3 + 1];
                w2 += psum[(q * TMC + tid) * 3 + 2];
            }
            float mean = 0.5f * (w0 + w1);
            float dd   = 0.5f * (w0 - w1);
            float rad  = sqrtf(dd * dd + w2 * w2);
            out[(size_t)gr * 2 + 0] = mean - rad;
            out[(size_t)gr * 2 + 1] = mean + rad;
        }
    }
}

extern "C" void kernel_launch(void* const* d_in, const int* in_sizes, int n_in,
                              void* d_out, int out_size)
{
    const float* x  = (const float*)d_in[0];
    const float* W1 = (const float*)d_in[1];
    const float* b1 = (const float*)d_in[2];
    const float* W2 = (const float*)d_in[3];
    const float* b2 = (const float*)d_in[4];
    const float* W3 = (const float*)d_in[5];
    const float* b3 = (const float*)d_in[6];
    float* out = (float*)d_out;

    int B = in_sizes[0] / 9;
    int grid = (B + TMC - 1) / TMC;

    prep_w2<<<64, 256>>>(W2);

    cudaFuncSetAttribute(nn_adiab_mma,
                         cudaFuncAttributeMaxDynamicSharedMemorySize, SMEM_BYTES);
    nn_adiab_mma<<<grid, NTHREADS, SMEM_BYTES>>>(x, W1, b1, b2, W3, b3, out, B);
}